// round 9
// baseline (speedup 1.0000x reference)
#include <cuda_runtime.h>

// SNN XORNet, T=20 LIF. Model (validated R8): fma-pipe cycle budget binds via the
// B300 RF-bank rule rt = max(2, #even_distinct, #odd_distinct): 3-source FFMA2 = rt 3.
// This round: the 10 beta-decay FFMA2s (compile-time 0.9 multiplier) become 2x scalar
// FFMA-imm each (rt=1, 0x823 form): pipe cost 3 -> 2 per pair. Reset stays packed sub2
// (rt 2), acc stays packed fma2 (w2 runtime). Each scalar half = identical IEEE fma.rn
// -> output bit-identical to R1-R8. Store: R8's single ulonglong2 STG.128.

#define T_STEPS 20
#define BETA    0.9f
#define THR     1.0f

typedef unsigned long long u64;

__device__ __forceinline__ u64 pack2(float lo, float hi) {
    u64 r; asm("mov.b64 %0, {%1, %2};" : "=l"(r) : "f"(lo), "f"(hi)); return r;
}
__device__ __forceinline__ void unpack2(u64 v, float& lo, float& hi) {
    asm("mov.b64 {%0, %1}, %2;" : "=f"(lo), "=f"(hi) : "l"(v));
}
__device__ __forceinline__ u64 fma2(u64 a, u64 b, u64 c) {
    u64 r; asm("fma.rn.f32x2 %0, %1, %2, %3;" : "=l"(r) : "l"(a), "l"(b), "l"(c)); return r;
}
__device__ __forceinline__ u64 sub2(u64 a, u64 b) {
    u64 r; asm("sub.rn.f32x2 %0, %1, %2;" : "=l"(r) : "l"(a), "l"(b)); return r;
}
__device__ __forceinline__ float fset_gt(float a, float b) {
    float r; asm("set.gt.f32.f32 %0, %1, %2;" : "=f"(r) : "f"(a), "f"(b)); return r;
}

__global__ __launch_bounds__(128)
void snn_kernel(const float* __restrict__ x,
                const float* __restrict__ w1,   // [4,2]
                const float* __restrict__ w2,   // [1,4]
                float* __restrict__ out,        // [T, B]
                int B)
{
    const int tid = blockIdx.x * blockDim.x + threadIdx.x;
    const int i0  = tid * 4;                    // 4 batch elements = 2 lane-pairs
    if (i0 >= B) return;

    float w1v[8];
#pragma unroll
    for (int k = 0; k < 8; k++) w1v[k] = __ldg(w1 + k);
    u64 w2p[4];
#pragma unroll
    for (int k = 0; k < 4; k++) { float w = __ldg(w2 + k); w2p[k] = pack2(w, w); }

    const float4* xv = reinterpret_cast<const float4*>(x + 2 * (size_t)i0);
    float4 xa = xv[0];
    float4 xb = xv[1];
    float xe[4][2] = {{xa.x, xa.y}, {xa.z, xa.w}, {xb.x, xb.y}, {xb.z, xb.w}};

    // cur (timestep-invariant) as scalar halves — same math as R1.
    float clo[2][4], chi[2][4];
#pragma unroll
    for (int p = 0; p < 2; p++)
#pragma unroll
        for (int h = 0; h < 4; h++) {
            clo[p][h] = fmaf(xe[2*p  ][1], w1v[2*h+1], xe[2*p  ][0] * w1v[2*h]);
            chi[p][h] = fmaf(xe[2*p+1][1], w1v[2*h+1], xe[2*p+1][0] * w1v[2*h]);
        }

    // Membranes as scalar halves (decay = FFMA-imm rt1); spikes packed for sub2/acc.
    float m1lo[2][4], m1hi[2][4], m2lo[2], m2hi[2];
    u64 s1[2][4], s2[2];
#pragma unroll
    for (int p = 0; p < 2; p++) {
#pragma unroll
        for (int h = 0; h < 4; h++) { m1lo[p][h] = 0.f; m1hi[p][h] = 0.f; s1[p][h] = 0ull; }
        m2lo[p] = 0.f; m2hi[p] = 0.f; s2[p] = 0ull;
    }

    float* outp = out + i0;
    const size_t stride = (size_t)B;

#pragma unroll   // full unroll (R6 win)
    for (int t = 0; t < T_STEPS; t++) {
#pragma unroll
        for (int p = 0; p < 2; p++) {
            u64 acc = 0ull;
#pragma unroll
            for (int h = 0; h < 4; h++) {
                // decay: scalar FFMA with immediate 0.9f multiplier (rt=1 each half)
                m1lo[p][h] = fmaf(BETA, m1lo[p][h], clo[p][h]);
                m1hi[p][h] = fmaf(BETA, m1hi[p][h], chi[p][h]);
                // reset: packed subtract of previous spike (rt=2), single rounding
                u64 mp = pack2(m1lo[p][h], m1hi[p][h]);
                mp = sub2(mp, s1[p][h]);
                unpack2(mp, m1lo[p][h], m1hi[p][h]);
                // spike + pack for the acc fma
                s1[p][h] = pack2(fset_gt(m1lo[p][h], THR), fset_gt(m1hi[p][h], THR));
                acc = fma2(s1[p][h], w2p[h], acc);     // out += spk1*w2 (seq order)
            }
            float alo, ahi; unpack2(acc, alo, ahi);
            m2lo[p] = fmaf(BETA, m2lo[p], alo);        // FFMA-imm
            m2hi[p] = fmaf(BETA, m2hi[p], ahi);
            u64 m2p = pack2(m2lo[p], m2hi[p]);
            m2p = sub2(m2p, s2[p]);
            unpack2(m2p, m2lo[p], m2hi[p]);
            s2[p] = pack2(fset_gt(m2lo[p], THR), fset_gt(m2hi[p], THR));
        }
        // one fully-coalesced 128-bit store, pairs already in memory order
        ulonglong2 ov; ov.x = s2[0]; ov.y = s2[1];
        *reinterpret_cast<ulonglong2*>(outp + (size_t)t * stride) = ov;
    }
}

extern "C" void kernel_launch(void* const* d_in, const int* in_sizes, int n_in,
                              void* d_out, int out_size)
{
    const float* x  = (const float*)d_in[0];   // [B,2]
    const float* w1 = (const float*)d_in[1];   // [4,2]
    const float* w2 = (const float*)d_in[2];   // [1,4]
    float* out = (float*)d_out;                // [T,B,1]

    const int B = in_sizes[0] / 2;             // 1,048,576
    const int elems_per_thread = 4;
    const int nthreads = (B + elems_per_thread - 1) / elems_per_thread;
    const int block = 128;
    const int grid = (nthreads + block - 1) / block;

    snn_kernel<<<grid, block>>>(x, w1, w2, out, B);
}